// round 16
// baseline (speedup 1.0000x reference)
#include <cuda_runtime.h>

#define RANK    64
#define WIN     11
#define TILE    256
#define THREADS 256
#define XS      268           // 67 words: odd -> conflict-free everywhere (verified)
#define NR4     67            // 268/4 row-quads stored (rows -5 .. 262 relative to tile)
#define PSS2    24            // pS row stride: 11 duplicated (p,p) pairs + pad

#define PS_OFF  (RANK * XS)                  // 17152
#define BS_OFF  (PS_OFF + TILE * PSS2)       // +6144
#define SMEM_FLOATS (BS_OFF + RANK)
#define SMEM_BYTES  (SMEM_FLOATS * 4)        // 93440 B -> 2 CTAs/SM

// tanh scale: 0.125 * log2(e) -> scores in log2 domain
#define VSCALE 0.18033688011112042f

// W in GEMV B-fragment layout, bf16 hi/lo split
__device__ uint2 g_WHI[2048];
__device__ uint2 g_WLO[2048];

static __device__ __forceinline__ unsigned pk2(float even, float odd) {
    unsigned d;
    asm("cvt.rn.bf16x2.f32 %0, %1, %2;" : "=r"(d) : "f"(odd), "f"(even));
    return d;
}
static __device__ __forceinline__ void split2(float a, float b, unsigned& h, unsigned& l) {
    h = pk2(a, b);
    float ha = __uint_as_float(h << 16);
    float hb = __uint_as_float(h & 0xffff0000u);
    l = pk2(a - ha, b - hb);
}
static __device__ __forceinline__ float tanhapx(float x) {
    float r; asm("tanh.approx.f32 %0, %1;" : "=f"(r) : "f"(x)); return r;
}
static __device__ __forceinline__ float ex2apx(float x) {
    float r; asm("ex2.approx.f32 %0, %1;" : "=f"(r) : "f"(x)); return r;
}
static __device__ __forceinline__ unsigned long long pack2(float lo, float hi) {
    unsigned long long r;
    asm("mov.b64 %0, {%1,%2};" : "=l"(r) : "f"(lo), "f"(hi));
    return r;
}
static __device__ __forceinline__ void unpack2(unsigned long long v, float& lo, float& hi) {
    asm("mov.b64 {%0,%1}, %2;" : "=f"(lo), "=f"(hi) : "l"(v));
}
static __device__ __forceinline__ void ffma2(unsigned long long& d,
                                             unsigned long long a, unsigned long long b) {
    asm("fma.rn.f32x2 %0, %1, %2, %0;" : "+l"(d) : "l"(a), "l"(b));
}
static __device__ __forceinline__ void mma16(float* d, const unsigned* a,
                                             unsigned b0, unsigned b1) {
    asm volatile(
        "mma.sync.aligned.m16n8k16.row.col.f32.bf16.bf16.f32 "
        "{%0,%1,%2,%3}, {%4,%5,%6,%7}, {%8,%9}, {%0,%1,%2,%3};"
        : "+f"(d[0]), "+f"(d[1]), "+f"(d[2]), "+f"(d[3])
        : "r"(a[0]), "r"(a[1]), "r"(a[2]), "r"(a[3]), "r"(b0), "r"(b1));
}

__global__ void prep_kernel(const float* __restrict__ W) {
    int e = blockIdx.x * 128 + threadIdx.x;     // 0..2047
    int lane = e & 31, set = e >> 5;
    int kc = set >> 3, nt = set & 7;
    int q = lane >> 2, t = lane & 3;
    int n = nt * 8 + q;
    int k0 = kc * 16 + 2 * t;
    float v0 = W[n * RANK + k0],     v1 = W[n * RANK + k0 + 1];
    float v2 = W[n * RANK + k0 + 8], v3 = W[n * RANK + k0 + 9];
    unsigned h01, l01, h23, l23;
    split2(v0, v1, h01, l01);
    split2(v2, v3, h23, l23);
    g_WHI[e] = make_uint2(h01, h23);
    g_WLO[e] = make_uint2(l01, l23);
}

__global__ __launch_bounds__(THREADS, 2)
void attn_w_kernel(const float* __restrict__ tf,
                   const float* __restrict__ b,
                   float* __restrict__ out,
                   int length)
{
    extern __shared__ float sm[];
    float* xsT = sm;            // [c][padded_row] stride XS
    float* pS  = sm + PS_OFF;   // [row][PSS2]
    float* bsh = sm + BS_OFF;

    const int tid  = threadIdx.x;
    const int wid  = tid >> 5;
    const int lane = tid & 31;
    const int q    = lane >> 2;
    const int t    = lane & 3;
    const int row0 = blockIdx.x * TILE;
    const int rbase = wid * 32;

    // ---- tile load: 4 coalesced LDG.32 per thread -> 1 STS.128 (conflict-free) ----
    for (int e = tid; e < NR4 * 64; e += THREADS) {
        int c = e & 63, r4 = e >> 6;
        int g0 = row0 - 5 + 4 * r4;
        float4 v;
        v.x = (g0     >= 0 && g0     < length) ? tf[g0 * RANK + c]       : 0.0f;
        v.y = (g0 + 1 >= 0 && g0 + 1 < length) ? tf[(g0 + 1) * RANK + c] : 0.0f;
        v.z = (g0 + 2 >= 0 && g0 + 2 < length) ? tf[(g0 + 2) * RANK + c] : 0.0f;
        v.w = (g0 + 3 >= 0 && g0 + 3 < length) ? tf[(g0 + 3) * RANK + c] : 0.0f;
        *(float4*)(xsT + c * XS + 4 * r4) = v;
    }
    if (tid < RANK) bsh[tid] = b[tid];
    __syncthreads();

    // ============ phase 1: per-warp 32 rows = two m16 tiles ============
    #pragma unroll 1
    for (int mi = 0; mi < 2; mi++) {
        // ---- GEMV via MMA: dv[nt][4] init with bias, 3-pass bf16 split ----
        float dv[8][4];
        #pragma unroll
        for (int nt = 0; nt < 8; nt++) {
            float2 bb = *(const float2*)(bsh + nt * 8 + 2 * t);
            dv[nt][0] = bb.x; dv[nt][1] = bb.y;
            dv[nt][2] = bb.x; dv[nt][3] = bb.y;
        }

        const int P = rbase + 16 * mi + 5 + q;      // padded row of A-row q
        #pragma unroll
        for (int kc = 0; kc < 4; kc++) {
            const int c0 = 16 * kc + 2 * t;
            float x0 = xsT[c0 * XS + P],           x1 = xsT[(c0 + 1) * XS + P];
            float x2 = xsT[c0 * XS + P + 8],       x3 = xsT[(c0 + 1) * XS + P + 8];
            float x4 = xsT[(c0 + 8) * XS + P],     x5 = xsT[(c0 + 9) * XS + P];
            float x6 = xsT[(c0 + 8) * XS + P + 8], x7 = xsT[(c0 + 9) * XS + P + 8];
            unsigned ah[4], al[4];
            split2(x0, x1, ah[0], al[0]);
            split2(x2, x3, ah[1], al[1]);
            split2(x4, x5, ah[2], al[2]);
            split2(x6, x7, ah[3], al[3]);
            #pragma unroll
            for (int nt = 0; nt < 8; nt++) {
                uint2 wh = g_WHI[(kc * 8 + nt) * 32 + lane];
                uint2 wl = g_WLO[(kc * 8 + nt) * 32 + lane];
                mma16(dv[nt], ah, wh.x, wh.y);
                mma16(dv[nt], al, wh.x, wh.y);
                mma16(dv[nt], ah, wl.x, wl.y);
            }
        }

        // ---- tanh (1 MUFU) + fold scale; re-split as score A-frags ----
        unsigned vh[8][2], vl[8][2];
        #pragma unroll
        for (int nt = 0; nt < 8; nt++) {
            #pragma unroll
            for (int r = 0; r < 4; r++)
                dv[nt][r] = tanhapx(dv[nt][r]) * VSCALE;
            split2(dv[nt][0], dv[nt][1], vh[nt][0], vl[nt][0]);  // row q
            split2(dv[nt][2], dv[nt][3], vh[nt][1], vl[nt][1]);  // row q+8
        }

        // ---- score MMA: 3 independent accumulator chains (depth 12 -> 4) ----
        #pragma unroll
        for (int nj = 0; nj < 4; nj++) {
            const int p = rbase + 16 * mi + 8 * nj + q;
            float dsA[4] = {0.f, 0.f, 0.f, 0.f};
            float dsB[4] = {0.f, 0.f, 0.f, 0.f};
            float dsC[4] = {0.f, 0.f, 0.f, 0.f};
            #pragma unroll
            for (int kc = 0; kc < 4; kc++) {
                const int c0 = 16 * kc + 2 * t;
                float y0 = xsT[c0 * XS + p],       y1 = xsT[(c0 + 1) * XS + p];
                float y2 = xsT[(c0 + 8) * XS + p], y3 = xsT[(c0 + 9) * XS + p];
                unsigned bh0, bl0, bh1, bl1;
                split2(y0, y1, bh0, bl0);
                split2(y2, y3, bh1, bl1);
                unsigned ah[4] = {vh[2 * kc][0], vh[2 * kc][1],
                                  vh[2 * kc + 1][0], vh[2 * kc + 1][1]};
                unsigned al[4] = {vl[2 * kc][0], vl[2 * kc][1],
                                  vl[2 * kc + 1][0], vl[2 * kc + 1][1]};
                mma16(dsA, ah, bh0, bh1);
                mma16(dsB, al, bh0, bh1);
                mma16(dsC, ah, bl0, bl1);
            }
            // band extraction: w = p_col - row
            #pragma unroll
            for (int r = 0; r < 4; r++) {
                int dr = r >> 1, dk = r & 1;
                int w = 8 * nj + 2 * t + dk - q - 8 * dr;
                if (w >= 0 && w < WIN)
                    pS[(rbase + 16 * mi + q + 8 * dr) * PSS2 + w] =
                        dsA[r] + dsB[r] + dsC[r];
            }
        }
    }
    __syncwarp();

    // ---- softmax (log2 domain) + write DUPLICATED (p,p) pairs ----
    {
        const float4* pr = (const float4*)(pS + tid * PSS2);
        float4 A = pr[0], B = pr[1], C = pr[2];
        float s[WIN] = {A.x, A.y, A.z, A.w, B.x, B.y, B.z, B.w, C.x, C.y, C.z};
        float mx = -1e30f;
        #pragma unroll
        for (int w = 0; w < WIN; w++) mx = fmaxf(mx, s[w]);
        float ssum = 0.0f;
        #pragma unroll
        for (int w = 0; w < WIN; w++) { s[w] = ex2apx(s[w] - mx); ssum += s[w]; }
        float inv = __fdividef(1.0f, ssum);
        #pragma unroll
        for (int w = 0; w < WIN; w++) s[w] *= inv;
        float4* pw4 = (float4*)(pS + tid * PSS2);
        pw4[0] = make_float4(s[0], s[0], s[1], s[1]);
        pw4[1] = make_float4(s[2], s[2], s[3], s[3]);
        pw4[2] = make_float4(s[4], s[4], s[5], s[5]);
        pw4[3] = make_float4(s[6], s[6], s[7], s[7]);
        pw4[4] = make_float4(s[8], s[8], s[9], s[9]);
        pw4[5] = make_float4(s[10], s[10], 0.0f, 0.0f);
    }
    __syncthreads();

    // ============ phase 2: packed f32x2 across column halves ============
    #pragma unroll 1
    for (int it = 0; it < TILE / 32; it++) {
        const int jj = 4 * wid + 32 * it;
        const float4* xqA = (const float4*)(xsT + lane * XS + jj);
        const float4* xqB = (const float4*)(xsT + (lane + 32) * XS + jj);
        float4 A0 = xqA[0], A1 = xqA[1], A2 = xqA[2], A3 = xqA[3];
        float4 B0 = xqB[0], B1 = xqB[1], B2 = xqB[2], B3 = xqB[3];
        float fxA[16] = {A0.x, A0.y, A0.z, A0.w, A1.x, A1.y, A1.z, A1.w,
                         A2.x, A2.y, A2.z, A2.w, A3.x, A3.y, A3.z, A3.w};
        float fxB[16] = {B0.x, B0.y, B0.z, B0.w, B1.x, B1.y, B1.z, B1.w,
                         B2.x, B2.y, B2.z, B2.w, B3.x, B3.y, B3.z, B3.w};
        unsigned long long px[14];
        #pragma unroll
        for (int k = 0; k < 14; k++) px[k] = pack2(fxA[k], fxB[k]);

        #pragma unroll
        for (int r = 0; r < 4; r++) {
            const double2* pq = (const double2*)(pS + (jj + r) * PSS2);
            double2 d0 = pq[0], d1 = pq[1], d2 = pq[2],
                    d3 = pq[3], d4 = pq[4], d5 = pq[5];
            unsigned long long pp[WIN] = {
                __double_as_longlong(d0.x), __double_as_longlong(d0.y),
                __double_as_longlong(d1.x), __double_as_longlong(d1.y),
                __double_as_longlong(d2.x), __double_as_longlong(d2.y),
                __double_as_longlong(d3.x), __double_as_longlong(d3.y),
                __double_as_longlong(d4.x), __double_as_longlong(d4.y),
                __double_as_longlong(d5.x)};
            unsigned long long acc = 0ull;
            #pragma unroll
            for (int w = 0; w < WIN; w++) ffma2(acc, px[r + w], pp[w]);
            float o0, o1;
            unpack2(acc, o0, o1);
            int gr = row0 + jj + r;
            if (gr < length) {
                out[gr * RANK + lane]      = o0;
                out[gr * RANK + lane + 32] = o1;
            }
        }
    }
}

extern "C" void kernel_launch(void* const* d_in, const int* in_sizes, int n_in,
                              void* d_out, int out_size)
{
    const float* tf = (const float*)d_in[0];
    const float* W  = (const float*)d_in[1];
    const float* b  = (const float*)d_in[2];
    float* out      = (float*)d_out;

    const int length = in_sizes[0] / RANK;
    const int grid   = (length + TILE - 1) / TILE;

    prep_kernel<<<16, 128>>>(W);
    cudaFuncSetAttribute(attn_w_kernel,
                         cudaFuncAttributeMaxDynamicSharedMemorySize, SMEM_BYTES);
    attn_w_kernel<<<grid, THREADS, SMEM_BYTES>>>(tf, b, out, length);
}